// round 3
// baseline (speedup 1.0000x reference)
#include <cuda_runtime.h>
#include <cuda_bf16.h>

// out = x + total, total = n*(n-1)/2 if n>1 else 0, n = trunc(sum(x)),
// x: 8192x8192 fp32 (64M elems, 256MB). DRAM floor 768MB, minus L2 carryover.
//
// R2 lessons applied:
//  - MLP: 4 front-batched independent loads per thread in both hot kernels.
//  - L2 carryover: pass1 reads front->back with evict-normal loads (tail of x
//    stays in 126MB L2); pass2 walks chunks back->front with streaming
//    loads/stores so its first ~100MB of x hits L2 instead of DRAM.

#define NBLOCKS 1184        // 148 SMs * 8 CTAs
#define NTHREADS 256

__device__ double g_partials[NBLOCKS];
__device__ float  g_total;

__global__ __launch_bounds__(NTHREADS)
void reduce_kernel(const float4* __restrict__ x4, long long n4) {
    float a0 = 0.f, a1 = 0.f, a2 = 0.f, a3 = 0.f;
    const long long stride = (long long)gridDim.x * blockDim.x;
    long long i = (long long)blockIdx.x * blockDim.x + threadIdx.x;

    // main loop: 4 independent loads in flight (MLP_p1=4)
    for (; i + 3 * stride < n4; i += 4 * stride) {
        float4 v0 = x4[i];
        float4 v1 = x4[i + stride];
        float4 v2 = x4[i + 2 * stride];
        float4 v3 = x4[i + 3 * stride];
        a0 += v0.x; a1 += v0.y; a2 += v0.z; a3 += v0.w;
        a0 += v1.x; a1 += v1.y; a2 += v1.z; a3 += v1.w;
        a0 += v2.x; a1 += v2.y; a2 += v2.z; a3 += v2.w;
        a0 += v3.x; a1 += v3.y; a2 += v3.z; a3 += v3.w;
    }
    for (; i < n4; i += stride) {
        float4 v = x4[i];
        a0 += v.x; a1 += v.y; a2 += v.z; a3 += v.w;
    }
    double acc = ((double)a0 + (double)a1) + ((double)a2 + (double)a3);

    __shared__ double s[NTHREADS];
    s[threadIdx.x] = acc;
    __syncthreads();
    #pragma unroll
    for (int off = NTHREADS / 2; off > 0; off >>= 1) {
        if (threadIdx.x < off) s[threadIdx.x] += s[threadIdx.x + off];
        __syncthreads();
    }
    if (threadIdx.x == 0) g_partials[blockIdx.x] = s[0];
}

__global__ __launch_bounds__(1024)
void finalize_kernel() {
    __shared__ double s[1024];
    double acc = 0.0;
    for (int i = threadIdx.x; i < NBLOCKS; i += 1024)
        acc += g_partials[i];
    s[threadIdx.x] = acc;
    __syncthreads();
    #pragma unroll
    for (int off = 512; off > 0; off >>= 1) {
        if (threadIdx.x < off) s[threadIdx.x] += s[threadIdx.x + off];
        __syncthreads();
    }
    if (threadIdx.x == 0) {
        double total_sum = s[0];
        double n = trunc(total_sum);      // int() truncates toward zero
        double total = (n > 1.0) ? n * (n - 1.0) * 0.5 : 0.0;
        g_total = (float)total;
    }
}

// Walks chunk-waves in REVERSE (high addresses first) to harvest pass-1's
// L2 residency. 4 independent loads per iteration.
__global__ __launch_bounds__(NTHREADS)
void add_kernel(const float4* __restrict__ x4, float4* __restrict__ o4,
                long long n4) {
    const float t = g_total;
    const long long stride = (long long)gridDim.x * blockDim.x;
    const long long tid = (long long)blockIdx.x * blockDim.x + threadIdx.x;
    const long long niter = (n4 + stride - 1) / stride;

    long long j = niter - 1;
    // top (possibly partial) chunk first — hottest in L2
    {
        long long i = j * stride + tid;
        if (i < n4) {
            float4 v = __ldcs(&x4[i]);
            v.x += t; v.y += t; v.z += t; v.w += t;
            __stcs(&o4[i], v);
        }
        j--;
    }
    // all remaining chunks are full; process 4 at a time, descending
    for (; j >= 3; j -= 4) {
        long long i0 = (j    ) * stride + tid;
        long long i1 = (j - 1) * stride + tid;
        long long i2 = (j - 2) * stride + tid;
        long long i3 = (j - 3) * stride + tid;
        float4 v0 = __ldcs(&x4[i0]);
        float4 v1 = __ldcs(&x4[i1]);
        float4 v2 = __ldcs(&x4[i2]);
        float4 v3 = __ldcs(&x4[i3]);
        v0.x += t; v0.y += t; v0.z += t; v0.w += t;
        v1.x += t; v1.y += t; v1.z += t; v1.w += t;
        v2.x += t; v2.y += t; v2.z += t; v2.w += t;
        v3.x += t; v3.y += t; v3.z += t; v3.w += t;
        __stcs(&o4[i0], v0);
        __stcs(&o4[i1], v1);
        __stcs(&o4[i2], v2);
        __stcs(&o4[i3], v3);
    }
    for (; j >= 0; j--) {
        long long i = j * stride + tid;
        float4 v = __ldcs(&x4[i]);
        v.x += t; v.y += t; v.z += t; v.w += t;
        __stcs(&o4[i], v);
    }
}

extern "C" void kernel_launch(void* const* d_in, const int* in_sizes, int n_in,
                              void* d_out, int out_size) {
    const float* x = (const float*)d_in[0];
    float* out = (float*)d_out;
    long long n = (long long)in_sizes[0];     // 67108864, divisible by 4
    long long n4 = n / 4;

    reduce_kernel<<<NBLOCKS, NTHREADS>>>((const float4*)x, n4);
    finalize_kernel<<<1, 1024>>>();
    add_kernel<<<NBLOCKS, NTHREADS>>>((const float4*)x, (float4*)out, n4);
}

// round 4
// speedup vs baseline: 1.0061x; 1.0061x over previous
#include <cuda_runtime.h>
#include <cuda_bf16.h>

// out = x + total, total = n*(n-1)/2 if n>1 else 0, n = trunc(sum(x)),
// x: 8192x8192 fp32 (64M elems, 256MB).
//
// R3 post-mortem applied:
//  - reverse-walk L2 harvest REVERTED (stores evict the tail anyway; -11us).
//  - reduce was occupancy-crippled (46 regs -> 5/8 CTAs per SM, ragged wave):
//    __launch_bounds__(256,8) forces <=32 regs, one clean wave.
//  - finalize fused into add: each CTA re-sums the 1184 partials from L2 in a
//    fixed order (deterministic, identical across CTAs/replays); saves a launch.

#define NBLOCKS 1184        // 148 SMs * 8 CTAs, single wave
#define NTHREADS 256

__device__ double g_partials[NBLOCKS];

__global__ __launch_bounds__(NTHREADS, 8)
void reduce_kernel(const float4* __restrict__ x4, long long n4) {
    float a0 = 0.f, a1 = 0.f, a2 = 0.f, a3 = 0.f;
    const long long stride = (long long)NBLOCKS * NTHREADS;
    long long i = (long long)blockIdx.x * NTHREADS + threadIdx.x;

    // 4 independent loads in flight
    for (; i + 3 * stride < n4; i += 4 * stride) {
        float4 v0 = x4[i];
        float4 v1 = x4[i + stride];
        float4 v2 = x4[i + 2 * stride];
        float4 v3 = x4[i + 3 * stride];
        a0 += v0.x; a1 += v0.y; a2 += v0.z; a3 += v0.w;
        a0 += v1.x; a1 += v1.y; a2 += v1.z; a3 += v1.w;
        a0 += v2.x; a1 += v2.y; a2 += v2.z; a3 += v2.w;
        a0 += v3.x; a1 += v3.y; a2 += v3.z; a3 += v3.w;
    }
    for (; i < n4; i += stride) {
        float4 v = x4[i];
        a0 += v.x; a1 += v.y; a2 += v.z; a3 += v.w;
    }
    double acc = ((double)a0 + (double)a1) + ((double)a2 + (double)a3);

    __shared__ double s[NTHREADS];
    s[threadIdx.x] = acc;
    __syncthreads();
    #pragma unroll
    for (int off = NTHREADS / 2; off > 0; off >>= 1) {
        if (threadIdx.x < off) s[threadIdx.x] += s[threadIdx.x + off];
        __syncthreads();
    }
    if (threadIdx.x == 0) g_partials[blockIdx.x] = s[0];
}

// Persistent forward-order add. Each CTA first re-derives the broadcast total
// from g_partials (fixed order -> deterministic, same value in every CTA).
__global__ __launch_bounds__(NTHREADS, 8)
void add_kernel(const float4* __restrict__ x4, float4* __restrict__ o4,
                long long n4) {
    __shared__ double s[NTHREADS];
    __shared__ float sh_total;
    {
        double acc = 0.0;
        #pragma unroll
        for (int i = threadIdx.x; i < NBLOCKS; i += NTHREADS)
            acc += g_partials[i];
        s[threadIdx.x] = acc;
        __syncthreads();
        #pragma unroll
        for (int off = NTHREADS / 2; off > 0; off >>= 1) {
            if (threadIdx.x < off) s[threadIdx.x] += s[threadIdx.x + off];
            __syncthreads();
        }
        if (threadIdx.x == 0) {
            double total_sum = s[0];
            double nn = trunc(total_sum);   // int() truncates toward zero
            sh_total = (float)((nn > 1.0) ? nn * (nn - 1.0) * 0.5 : 0.0);
        }
        __syncthreads();
    }
    const float t = sh_total;

    const long long stride = (long long)NBLOCKS * NTHREADS;
    long long i = (long long)blockIdx.x * NTHREADS + threadIdx.x;
    for (; i + 3 * stride < n4; i += 4 * stride) {
        float4 v0 = x4[i];
        float4 v1 = x4[i + stride];
        float4 v2 = x4[i + 2 * stride];
        float4 v3 = x4[i + 3 * stride];
        v0.x += t; v0.y += t; v0.z += t; v0.w += t;
        v1.x += t; v1.y += t; v1.z += t; v1.w += t;
        v2.x += t; v2.y += t; v2.z += t; v2.w += t;
        v3.x += t; v3.y += t; v3.z += t; v3.w += t;
        o4[i] = v0;
        o4[i + stride] = v1;
        o4[i + 2 * stride] = v2;
        o4[i + 3 * stride] = v3;
    }
    for (; i < n4; i += stride) {
        float4 v = x4[i];
        v.x += t; v.y += t; v.z += t; v.w += t;
        o4[i] = v;
    }
}

extern "C" void kernel_launch(void* const* d_in, const int* in_sizes, int n_in,
                              void* d_out, int out_size) {
    const float* x = (const float*)d_in[0];
    float* out = (float*)d_out;
    long long n = (long long)in_sizes[0];     // 67108864, divisible by 4
    long long n4 = n / 4;

    reduce_kernel<<<NBLOCKS, NTHREADS>>>((const float4*)x, n4);
    add_kernel<<<NBLOCKS, NTHREADS>>>((const float4*)x, (float4*)out, n4);
}

// round 5
// speedup vs baseline: 1.0837x; 1.0771x over previous
#include <cuda_runtime.h>
#include <cuda_bf16.h>

// out = x + total, total = n*(n-1)/2 if n>1 else 0, n = trunc(sum(x)),
// x: 8192x8192 fp32 (64M elems, 256MB).
//
// R4 post-mortem applied:
//  - reduce: occupancy clamp REVERTED (MLP-bound; 46 regs/occ52% beat 32/occ90%).
//  - add: __stcs stores restored (worth ~9us), forward order kept.
//  - L2 carryover, producer-side: reduce walks x BACKWARD so L2 ends holding
//    the FRONT of x; add walks FORWARD and harvests it. Streaming (.cs)
//    stores in add are evict-first so they don't flush the resident x lines.
//  - finalize stays fused into add (deterministic fixed-order re-sum per CTA).

#define NBLOCKS 1184        // 148 SMs * 8 CTAs
#define NTHREADS 256

__device__ double g_partials[NBLOCKS];

__global__ __launch_bounds__(NTHREADS)
void reduce_kernel(const float4* __restrict__ x4, long long n4) {
    float a0 = 0.f, a1 = 0.f, a2 = 0.f, a3 = 0.f;
    const long long stride = (long long)NBLOCKS * NTHREADS;
    const long long tid = (long long)blockIdx.x * NTHREADS + threadIdx.x;
    const long long niter = (n4 + stride - 1) / stride;

    long long j = niter - 1;
    // top (possibly partial) chunk
    {
        long long i = j * stride + tid;
        if (i < n4) {
            float4 v = x4[i];
            a0 += v.x; a1 += v.y; a2 += v.z; a3 += v.w;
        }
        j--;
    }
    // descending full chunks, 4 independent loads in flight
    for (; j >= 3; j -= 4) {
        float4 v0 = x4[(j    ) * stride + tid];
        float4 v1 = x4[(j - 1) * stride + tid];
        float4 v2 = x4[(j - 2) * stride + tid];
        float4 v3 = x4[(j - 3) * stride + tid];
        a0 += v0.x; a1 += v0.y; a2 += v0.z; a3 += v0.w;
        a0 += v1.x; a1 += v1.y; a2 += v1.z; a3 += v1.w;
        a0 += v2.x; a1 += v2.y; a2 += v2.z; a3 += v2.w;
        a0 += v3.x; a1 += v3.y; a2 += v3.z; a3 += v3.w;
    }
    for (; j >= 0; j--) {
        float4 v = x4[j * stride + tid];
        a0 += v.x; a1 += v.y; a2 += v.z; a3 += v.w;
    }
    double acc = ((double)a0 + (double)a1) + ((double)a2 + (double)a3);

    __shared__ double s[NTHREADS];
    s[threadIdx.x] = acc;
    __syncthreads();
    #pragma unroll
    for (int off = NTHREADS / 2; off > 0; off >>= 1) {
        if (threadIdx.x < off) s[threadIdx.x] += s[threadIdx.x + off];
        __syncthreads();
    }
    if (threadIdx.x == 0) g_partials[blockIdx.x] = s[0];
}

// Forward persistent add. Each CTA re-derives the broadcast total from
// g_partials in a fixed order (deterministic, identical across CTAs/replays).
// x loads: default policy (harvest L2 residency from the backward reduce).
// out stores: streaming evict-first.
__global__ __launch_bounds__(NTHREADS)
void add_kernel(const float4* __restrict__ x4, float4* __restrict__ o4,
                long long n4) {
    __shared__ double s[NTHREADS];
    __shared__ float sh_total;
    {
        double acc = 0.0;
        #pragma unroll
        for (int i = threadIdx.x; i < NBLOCKS; i += NTHREADS)
            acc += g_partials[i];
        s[threadIdx.x] = acc;
        __syncthreads();
        #pragma unroll
        for (int off = NTHREADS / 2; off > 0; off >>= 1) {
            if (threadIdx.x < off) s[threadIdx.x] += s[threadIdx.x + off];
            __syncthreads();
        }
        if (threadIdx.x == 0) {
            double total_sum = s[0];
            double nn = trunc(total_sum);   // int() truncates toward zero
            sh_total = (float)((nn > 1.0) ? nn * (nn - 1.0) * 0.5 : 0.0);
        }
        __syncthreads();
    }
    const float t = sh_total;

    const long long stride = (long long)NBLOCKS * NTHREADS;
    long long i = (long long)blockIdx.x * NTHREADS + threadIdx.x;
    for (; i + 3 * stride < n4; i += 4 * stride) {
        float4 v0 = x4[i];
        float4 v1 = x4[i + stride];
        float4 v2 = x4[i + 2 * stride];
        float4 v3 = x4[i + 3 * stride];
        v0.x += t; v0.y += t; v0.z += t; v0.w += t;
        v1.x += t; v1.y += t; v1.z += t; v1.w += t;
        v2.x += t; v2.y += t; v2.z += t; v2.w += t;
        v3.x += t; v3.y += t; v3.z += t; v3.w += t;
        __stcs(&o4[i], v0);
        __stcs(&o4[i + stride], v1);
        __stcs(&o4[i + 2 * stride], v2);
        __stcs(&o4[i + 3 * stride], v3);
    }
    for (; i < n4; i += stride) {
        float4 v = x4[i];
        v.x += t; v.y += t; v.z += t; v.w += t;
        __stcs(&o4[i], v);
    }
}

extern "C" void kernel_launch(void* const* d_in, const int* in_sizes, int n_in,
                              void* d_out, int out_size) {
    const float* x = (const float*)d_in[0];
    float* out = (float*)d_out;
    long long n = (long long)in_sizes[0];     // 67108864, divisible by 4
    long long n4 = n / 4;

    reduce_kernel<<<NBLOCKS, NTHREADS>>>((const float4*)x, n4);
    add_kernel<<<NBLOCKS, NTHREADS>>>((const float4*)x, (float4*)out, n4);
}

// round 6
// speedup vs baseline: 1.1169x; 1.0306x over previous
#include <cuda_runtime.h>
#include <cuda_bf16.h>

// out = x + total, total = n*(n-1)/2 if n>1 else 0, n = trunc(sum(x)),
// x: 8192x8192 fp32 (64M elems, 256MB).
//
// R5 post-mortem applied:
//  - RAGGED WAVES were taxing both kernels (grid=1184 but only 5-6 CTAs/SM
//    resident -> straggler tail with idle machine). Now exact single waves:
//    reduce grid = 148*5 = 740 (launch_bounds 256,5 -> 51-reg budget),
//    add    grid = 148*6 = 888 (launch_bounds 256,6 -> 42-reg budget).
//  - Kept: backward reduce / forward add L2 carryover, .cs streaming stores,
//    fused deterministic finalize, MLP=4 front-batched loads.

#define NTHREADS 256
#define RED_BLOCKS 740      // 148 SMs * 5 CTAs — one exact wave
#define ADD_BLOCKS 888      // 148 SMs * 6 CTAs — one exact wave

__device__ double g_partials[RED_BLOCKS];

__global__ __launch_bounds__(NTHREADS, 5)
void reduce_kernel(const float4* __restrict__ x4, long long n4) {
    float a0 = 0.f, a1 = 0.f, a2 = 0.f, a3 = 0.f;
    const long long stride = (long long)RED_BLOCKS * NTHREADS;
    const long long tid = (long long)blockIdx.x * NTHREADS + threadIdx.x;
    const long long niter = (n4 + stride - 1) / stride;

    long long j = niter - 1;
    // top (possibly partial) chunk; walk BACKWARD so L2 ends holding x's front
    {
        long long i = j * stride + tid;
        if (i < n4) {
            float4 v = x4[i];
            a0 += v.x; a1 += v.y; a2 += v.z; a3 += v.w;
        }
        j--;
    }
    for (; j >= 3; j -= 4) {
        float4 v0 = x4[(j    ) * stride + tid];
        float4 v1 = x4[(j - 1) * stride + tid];
        float4 v2 = x4[(j - 2) * stride + tid];
        float4 v3 = x4[(j - 3) * stride + tid];
        a0 += v0.x; a1 += v0.y; a2 += v0.z; a3 += v0.w;
        a0 += v1.x; a1 += v1.y; a2 += v1.z; a3 += v1.w;
        a0 += v2.x; a1 += v2.y; a2 += v2.z; a3 += v2.w;
        a0 += v3.x; a1 += v3.y; a2 += v3.z; a3 += v3.w;
    }
    for (; j >= 0; j--) {
        float4 v = x4[j * stride + tid];
        a0 += v.x; a1 += v.y; a2 += v.z; a3 += v.w;
    }
    double acc = ((double)a0 + (double)a1) + ((double)a2 + (double)a3);

    __shared__ double s[NTHREADS];
    s[threadIdx.x] = acc;
    __syncthreads();
    #pragma unroll
    for (int off = NTHREADS / 2; off > 0; off >>= 1) {
        if (threadIdx.x < off) s[threadIdx.x] += s[threadIdx.x + off];
        __syncthreads();
    }
    if (threadIdx.x == 0) g_partials[blockIdx.x] = s[0];
}

// Forward persistent add, exact single wave. Each CTA re-derives the
// broadcast total from g_partials in a fixed order (deterministic).
__global__ __launch_bounds__(NTHREADS, 6)
void add_kernel(const float4* __restrict__ x4, float4* __restrict__ o4,
                long long n4) {
    __shared__ double s[NTHREADS];
    __shared__ float sh_total;
    {
        double acc = 0.0;
        #pragma unroll
        for (int i = threadIdx.x; i < RED_BLOCKS; i += NTHREADS)
            acc += g_partials[i];
        s[threadIdx.x] = acc;
        __syncthreads();
        #pragma unroll
        for (int off = NTHREADS / 2; off > 0; off >>= 1) {
            if (threadIdx.x < off) s[threadIdx.x] += s[threadIdx.x + off];
            __syncthreads();
        }
        if (threadIdx.x == 0) {
            double total_sum = s[0];
            double nn = trunc(total_sum);   // int() truncates toward zero
            sh_total = (float)((nn > 1.0) ? nn * (nn - 1.0) * 0.5 : 0.0);
        }
        __syncthreads();
    }
    const float t = sh_total;

    const long long stride = (long long)ADD_BLOCKS * NTHREADS;
    long long i = (long long)blockIdx.x * NTHREADS + threadIdx.x;
    for (; i + 3 * stride < n4; i += 4 * stride) {
        float4 v0 = x4[i];
        float4 v1 = x4[i + stride];
        float4 v2 = x4[i + 2 * stride];
        float4 v3 = x4[i + 3 * stride];
        v0.x += t; v0.y += t; v0.z += t; v0.w += t;
        v1.x += t; v1.y += t; v1.z += t; v1.w += t;
        v2.x += t; v2.y += t; v2.z += t; v2.w += t;
        v3.x += t; v3.y += t; v3.z += t; v3.w += t;
        __stcs(&o4[i], v0);
        __stcs(&o4[i + stride], v1);
        __stcs(&o4[i + 2 * stride], v2);
        __stcs(&o4[i + 3 * stride], v3);
    }
    for (; i < n4; i += stride) {
        float4 v = x4[i];
        v.x += t; v.y += t; v.z += t; v.w += t;
        __stcs(&o4[i], v);
    }
}

extern "C" void kernel_launch(void* const* d_in, const int* in_sizes, int n_in,
                              void* d_out, int out_size) {
    const float* x = (const float*)d_in[0];
    float* out = (float*)d_out;
    long long n = (long long)in_sizes[0];     // 67108864, divisible by 4
    long long n4 = n / 4;

    reduce_kernel<<<RED_BLOCKS, NTHREADS>>>((const float4*)x, n4);
    add_kernel<<<ADD_BLOCKS, NTHREADS>>>((const float4*)x, (float4*)out, n4);
}

// round 7
// speedup vs baseline: 1.1391x; 1.0198x over previous
#include <cuda_runtime.h>
#include <cuda_bf16.h>

// out = x + total, total = n*(n-1)/2 if n>1 else 0, n = trunc(sum(x)),
// x: 8192x8192 fp32 (64M elems, 256MB).
//
// R6 post-mortem applied:
//  - reduce kept (740 CTAs, clamp 5, backward walk, MLP4 -> ~6.1 TB/s).
//  - add was MLP-limited, not wave-limited (888 single wave regressed vs 1184).
//    Now: single wave 740 CTAs @ clamp 5 (51-reg budget) with MLP=8 —
//    8 front-batched independent float4 loads + 8 .cs stores per iteration.

#define NTHREADS 256
#define RED_BLOCKS 740      // 148 SMs * 5 CTAs — one exact wave
#define ADD_BLOCKS 740      // 148 SMs * 5 CTAs — one exact wave, 8-deep MLP

__device__ double g_partials[RED_BLOCKS];

__global__ __launch_bounds__(NTHREADS, 5)
void reduce_kernel(const float4* __restrict__ x4, long long n4) {
    float a0 = 0.f, a1 = 0.f, a2 = 0.f, a3 = 0.f;
    const long long stride = (long long)RED_BLOCKS * NTHREADS;
    const long long tid = (long long)blockIdx.x * NTHREADS + threadIdx.x;
    const long long niter = (n4 + stride - 1) / stride;

    long long j = niter - 1;
    // top (possibly partial) chunk; walk BACKWARD so L2 ends holding x's front
    {
        long long i = j * stride + tid;
        if (i < n4) {
            float4 v = x4[i];
            a0 += v.x; a1 += v.y; a2 += v.z; a3 += v.w;
        }
        j--;
    }
    for (; j >= 3; j -= 4) {
        float4 v0 = x4[(j    ) * stride + tid];
        float4 v1 = x4[(j - 1) * stride + tid];
        float4 v2 = x4[(j - 2) * stride + tid];
        float4 v3 = x4[(j - 3) * stride + tid];
        a0 += v0.x; a1 += v0.y; a2 += v0.z; a3 += v0.w;
        a0 += v1.x; a1 += v1.y; a2 += v1.z; a3 += v1.w;
        a0 += v2.x; a1 += v2.y; a2 += v2.z; a3 += v2.w;
        a0 += v3.x; a1 += v3.y; a2 += v3.z; a3 += v3.w;
    }
    for (; j >= 0; j--) {
        float4 v = x4[j * stride + tid];
        a0 += v.x; a1 += v.y; a2 += v.z; a3 += v.w;
    }
    double acc = ((double)a0 + (double)a1) + ((double)a2 + (double)a3);

    __shared__ double s[NTHREADS];
    s[threadIdx.x] = acc;
    __syncthreads();
    #pragma unroll
    for (int off = NTHREADS / 2; off > 0; off >>= 1) {
        if (threadIdx.x < off) s[threadIdx.x] += s[threadIdx.x + off];
        __syncthreads();
    }
    if (threadIdx.x == 0) g_partials[blockIdx.x] = s[0];
}

// Forward persistent add, single wave, MLP=8. Each CTA re-derives the
// broadcast total from g_partials in a fixed order (deterministic).
__global__ __launch_bounds__(NTHREADS, 5)
void add_kernel(const float4* __restrict__ x4, float4* __restrict__ o4,
                long long n4) {
    __shared__ double s[NTHREADS];
    __shared__ float sh_total;
    {
        double acc = 0.0;
        #pragma unroll
        for (int i = threadIdx.x; i < RED_BLOCKS; i += NTHREADS)
            acc += g_partials[i];
        s[threadIdx.x] = acc;
        __syncthreads();
        #pragma unroll
        for (int off = NTHREADS / 2; off > 0; off >>= 1) {
            if (threadIdx.x < off) s[threadIdx.x] += s[threadIdx.x + off];
            __syncthreads();
        }
        if (threadIdx.x == 0) {
            double total_sum = s[0];
            double nn = trunc(total_sum);   // int() truncates toward zero
            sh_total = (float)((nn > 1.0) ? nn * (nn - 1.0) * 0.5 : 0.0);
        }
        __syncthreads();
    }
    const float t = sh_total;

    const long long stride = (long long)ADD_BLOCKS * NTHREADS;
    long long i = (long long)blockIdx.x * NTHREADS + threadIdx.x;

    // MLP=8 main loop: 8 independent loads, 8 adds, 8 streaming stores
    for (; i + 7 * stride < n4; i += 8 * stride) {
        float4 v0 = x4[i];
        float4 v1 = x4[i + stride];
        float4 v2 = x4[i + 2 * stride];
        float4 v3 = x4[i + 3 * stride];
        float4 v4 = x4[i + 4 * stride];
        float4 v5 = x4[i + 5 * stride];
        float4 v6 = x4[i + 6 * stride];
        float4 v7 = x4[i + 7 * stride];
        v0.x += t; v0.y += t; v0.z += t; v0.w += t;
        v1.x += t; v1.y += t; v1.z += t; v1.w += t;
        v2.x += t; v2.y += t; v2.z += t; v2.w += t;
        v3.x += t; v3.y += t; v3.z += t; v3.w += t;
        v4.x += t; v4.y += t; v4.z += t; v4.w += t;
        v5.x += t; v5.y += t; v5.z += t; v5.w += t;
        v6.x += t; v6.y += t; v6.z += t; v6.w += t;
        v7.x += t; v7.y += t; v7.z += t; v7.w += t;
        __stcs(&o4[i], v0);
        __stcs(&o4[i + stride], v1);
        __stcs(&o4[i + 2 * stride], v2);
        __stcs(&o4[i + 3 * stride], v3);
        __stcs(&o4[i + 4 * stride], v4);
        __stcs(&o4[i + 5 * stride], v5);
        __stcs(&o4[i + 6 * stride], v6);
        __stcs(&o4[i + 7 * stride], v7);
    }
    for (; i < n4; i += stride) {
        float4 v = x4[i];
        v.x += t; v.y += t; v.z += t; v.w += t;
        __stcs(&o4[i], v);
    }
}

extern "C" void kernel_launch(void* const* d_in, const int* in_sizes, int n_in,
                              void* d_out, int out_size) {
    const float* x = (const float*)d_in[0];
    float* out = (float*)d_out;
    long long n = (long long)in_sizes[0];     // 67108864, divisible by 4
    long long n4 = n / 4;

    reduce_kernel<<<RED_BLOCKS, NTHREADS>>>((const float4*)x, n4);
    add_kernel<<<ADD_BLOCKS, NTHREADS>>>((const float4*)x, (float4*)out, n4);
}

// round 8
// speedup vs baseline: 1.1764x; 1.0328x over previous
#include <cuda_runtime.h>
#include <cuda_bf16.h>

// out = x + total, total = n*(n-1)/2 if n>1 else 0, n = trunc(sum(x)),
// x: 8192x8192 fp32 (64M elems, 256MB).
//
// R7 post-mortem applied:
//  - add reverted to the best-measured shape: NON-persistent, one float4 per
//    thread, __ldcs loads + __stcs stores (contiguous concurrent window ->
//    better DRAM page locality for the mixed read/write stream).
//  - finalize fused into reduce via last-block pattern (atomic arrival
//    counter, reset by the finisher for graph-replay safety). The final sum
//    is computed in a FIXED order -> deterministic output every replay.
//  - reduce keeps: 740 CTAs (one exact wave @ clamp 5), backward walk
//    (leaves x's front in L2 for the add), MLP=4 front-batched loads.

#define NTHREADS 256
#define RED_BLOCKS 740      // 148 SMs * 5 CTAs — one exact wave

__device__ double g_partials[RED_BLOCKS];
__device__ float g_total;
__device__ unsigned int g_arrive;   // zero-init; finisher resets each launch

__global__ __launch_bounds__(NTHREADS, 5)
void reduce_kernel(const float4* __restrict__ x4, long long n4) {
    float a0 = 0.f, a1 = 0.f, a2 = 0.f, a3 = 0.f;
    const long long stride = (long long)RED_BLOCKS * NTHREADS;
    const long long tid = (long long)blockIdx.x * NTHREADS + threadIdx.x;
    const long long niter = (n4 + stride - 1) / stride;

    long long j = niter - 1;
    // top (possibly partial) chunk; walk BACKWARD so L2 ends holding x's front
    {
        long long i = j * stride + tid;
        if (i < n4) {
            float4 v = x4[i];
            a0 += v.x; a1 += v.y; a2 += v.z; a3 += v.w;
        }
        j--;
    }
    for (; j >= 3; j -= 4) {
        float4 v0 = x4[(j    ) * stride + tid];
        float4 v1 = x4[(j - 1) * stride + tid];
        float4 v2 = x4[(j - 2) * stride + tid];
        float4 v3 = x4[(j - 3) * stride + tid];
        a0 += v0.x; a1 += v0.y; a2 += v0.z; a3 += v0.w;
        a0 += v1.x; a1 += v1.y; a2 += v1.z; a3 += v1.w;
        a0 += v2.x; a1 += v2.y; a2 += v2.z; a3 += v2.w;
        a0 += v3.x; a1 += v3.y; a2 += v3.z; a3 += v3.w;
    }
    for (; j >= 0; j--) {
        float4 v = x4[j * stride + tid];
        a0 += v.x; a1 += v.y; a2 += v.z; a3 += v.w;
    }
    double acc = ((double)a0 + (double)a1) + ((double)a2 + (double)a3);

    __shared__ double s[NTHREADS];
    s[threadIdx.x] = acc;
    __syncthreads();
    #pragma unroll
    for (int off = NTHREADS / 2; off > 0; off >>= 1) {
        if (threadIdx.x < off) s[threadIdx.x] += s[threadIdx.x + off];
        __syncthreads();
    }

    __shared__ int is_last;
    if (threadIdx.x == 0) {
        g_partials[blockIdx.x] = s[0];
        __threadfence();                       // partial visible GPU-wide
        unsigned int prev = atomicAdd(&g_arrive, 1u);
        is_last = (prev == RED_BLOCKS - 1);
        if (is_last) atomicExch(&g_arrive, 0u);  // reset for next graph replay
    }
    __syncthreads();

    // Last-arriving CTA finalizes. Sum order is FIXED (i ascending, strided
    // lanes + tree) -> identical result no matter which CTA is last.
    if (is_last) {
        double acc2 = 0.0;
        #pragma unroll
        for (int i = threadIdx.x; i < RED_BLOCKS; i += NTHREADS)
            acc2 += g_partials[i];
        s[threadIdx.x] = acc2;
        __syncthreads();
        #pragma unroll
        for (int off = NTHREADS / 2; off > 0; off >>= 1) {
            if (threadIdx.x < off) s[threadIdx.x] += s[threadIdx.x + off];
            __syncthreads();
        }
        if (threadIdx.x == 0) {
            double total_sum = s[0];
            double nn = trunc(total_sum);   // int() truncates toward zero
            g_total = (float)((nn > 1.0) ? nn * (nn - 1.0) * 0.5 : 0.0);
        }
    }
}

// Non-persistent streaming add: one float4 per thread, contiguous concurrent
// address window -> best DRAM page locality for the mixed r/w stream.
__global__ __launch_bounds__(NTHREADS)
void add_kernel(const float4* __restrict__ x4, float4* __restrict__ o4,
                long long n4) {
    const float t = g_total;
    long long i = (long long)blockIdx.x * NTHREADS + threadIdx.x;
    if (i < n4) {
        float4 v = __ldcs(&x4[i]);
        v.x += t; v.y += t; v.z += t; v.w += t;
        __stcs(&o4[i], v);
    }
}

extern "C" void kernel_launch(void* const* d_in, const int* in_sizes, int n_in,
                              void* d_out, int out_size) {
    const float* x = (const float*)d_in[0];
    float* out = (float*)d_out;
    long long n = (long long)in_sizes[0];     // 67108864, divisible by 4
    long long n4 = n / 4;

    reduce_kernel<<<RED_BLOCKS, NTHREADS>>>((const float4*)x, n4);
    long long add_blocks = (n4 + NTHREADS - 1) / NTHREADS;
    add_kernel<<<(unsigned)add_blocks, NTHREADS>>>((const float4*)x,
                                                   (float4*)out, n4);
}